// round 2
// baseline (speedup 1.0000x reference)
#include <cuda_runtime.h>
#include <math.h>

#define Bc 128
#define Pc 4096
#define Fc 32
#define Kc 8
#define Dc 64
#define ITERS_C 2

typedef unsigned long long ull;

// ---------------- scratch (static __device__, no runtime alloc) ----------------
__device__ float g_kT[(size_t)Bc * Dc * Pc];   // K transposed: [B][D][P]
__device__ float g_v[(size_t)Bc * Pc * Dc];    // V: [B][P][D]
__device__ float g_slots[Bc * Kc * Dc];
__device__ float g_q[Bc * Kc * Dc];
__device__ float g_upd[Bc * Kc * Dc];
__device__ float g_S[Bc * Kc];
__device__ float g_WqT[Dc * Dc];               // [e][d]
__device__ float g_WihT[Dc * 3 * Dc];          // [e][j], stride 192
__device__ float g_WhhT[Dc * 3 * Dc];          // [e][j], stride 192
__device__ float g_W1T[Dc * 2 * Dc];           // [e][j], stride 128
__device__ float g_W2T[2 * Dc * Dc];           // [j][d], stride 64

// ---------------- packed f32x2 helpers ----------------
__device__ __forceinline__ ull fma2(ull a, ull b, ull c) {
    ull d;
    asm("fma.rn.f32x2 %0, %1, %2, %3;" : "=l"(d) : "l"(a), "l"(b), "l"(c));
    return d;
}
__device__ __forceinline__ ull pack2(float x, float y) {
    ull r;
    asm("mov.b64 %0, {%1, %2};" : "=l"(r) : "f"(x), "f"(y));
    return r;
}
__device__ __forceinline__ float2 unpack2(ull v) {
    float2 r;
    asm("mov.b64 {%0, %1}, %2;" : "=f"(r.x), "=f"(r.y) : "l"(v));
    return r;
}

// ---------------- init: slots init + weight transposes ----------------
__global__ void k_init(const float* __restrict__ noise, const float* __restrict__ mu,
                       const float* __restrict__ sigma, const float* __restrict__ Wq,
                       const float* __restrict__ Wih, const float* __restrict__ Whh,
                       const float* __restrict__ W1, const float* __restrict__ W2) {
    int i = blockIdx.x * blockDim.x + threadIdx.x;  // 0..65535
    if (i < Bc * Kc * Dc) {
        int d = i & 63;
        g_slots[i] = mu[d] + fabsf(sigma[d]) * noise[i];
    }
    if (i < Dc * Dc) {  // Wq [64,64] -> [e][d]
        g_WqT[(i & 63) * Dc + (i >> 6)] = Wq[i];
    }
    if (i < 3 * Dc * Dc) {  // [192,64] -> [e][j]
        int j = i >> 6, e = i & 63;
        g_WihT[e * 192 + j] = Wih[i];
        g_WhhT[e * 192 + j] = Whh[i];
    }
    if (i < 2 * Dc * Dc) {  // ff_W1 [128,64] -> [e][j]
        int j = i >> 6, e = i & 63;
        g_W1T[e * 128 + j] = W1[i];
    }
    if (i < 2 * Dc * Dc) {  // ff_W2 [64,128] -> [j][d]
        int dd = i >> 7, j = i & 127;
        g_W2T[j * 64 + dd] = W2[i];
    }
}

// ---------------- LayerNorm(x) + K/V projection ----------------
__global__ void __launch_bounds__(256) k_proj(const float* __restrict__ x,
                                              const float* __restrict__ Wk,
                                              const float* __restrict__ Wv,
                                              const float* __restrict__ lg,
                                              const float* __restrict__ lb) {
    __shared__ float sW[Fc][128];  // [f][0..63]=WkT, [f][64..127]=WvT
    __shared__ float sg[Fc], sb[Fc];
    int t = threadIdx.x;
    for (int i = t; i < Dc * Fc; i += 256) {
        int d = i >> 5, f = i & 31;
        sW[f][d] = Wk[i];
        sW[f][64 + d] = Wv[i];
    }
    if (t < Fc) { sg[t] = lg[t]; sb[t] = lb[t]; }
    __syncthreads();

    size_t gp = (size_t)blockIdx.x * 256 + t;  // global pixel in [0, B*P)
    int b = (int)(gp >> 12);
    int p = (int)(gp & 4095);

    const float4* xr4 = (const float4*)(x + gp * Fc);
    float xv[32];
#pragma unroll
    for (int j = 0; j < 8; j++) {
        float4 q = xr4[j];
        xv[4 * j] = q.x; xv[4 * j + 1] = q.y; xv[4 * j + 2] = q.z; xv[4 * j + 3] = q.w;
    }
    float m = 0.f;
#pragma unroll
    for (int f = 0; f < 32; f++) m += xv[f];
    m *= (1.f / 32.f);
    float var = 0.f;
#pragma unroll
    for (int f = 0; f < 32; f++) { float dv = xv[f] - m; var += dv * dv; }
    var *= (1.f / 32.f);
    float rstd = rsqrtf(var + 1e-5f);
#pragma unroll
    for (int f = 0; f < 32; f++) xv[f] = (xv[f] - m) * rstd * sg[f] + sb[f];

#pragma unroll
    for (int c = 0; c < 4; c++) {  // 4 chunks of 32 outputs (16 pairs)
        ull acc[16];
#pragma unroll
        for (int j = 0; j < 16; j++) acc[j] = 0ULL;
#pragma unroll 4
        for (int f = 0; f < 32; f++) {
            ull xx = pack2(xv[f], xv[f]);
            const ull* w2 = (const ull*)&sW[f][32 * c];
#pragma unroll
            for (int j = 0; j < 16; j++) acc[j] = fma2(xx, w2[j], acc[j]);
        }
        if (c < 2) {  // K -> transposed layout [B][D][P]
#pragma unroll
            for (int j = 0; j < 16; j++) {
                float2 r = unpack2(acc[j]);
                int d = 32 * c + 2 * j;
                g_kT[((size_t)b * Dc + d) * Pc + p] = r.x;
                g_kT[((size_t)b * Dc + d + 1) * Pc + p] = r.y;
            }
        } else {  // V -> [B][P][D]
            ull* vr = (ull*)(g_v + gp * Dc + 32 * (c - 2));
#pragma unroll
            for (int j = 0; j < 16; j++) vr[j] = acc[j];
        }
    }
}

// ---------------- q = LN(slots) @ Wq^T; zero S and upd ----------------
__global__ void k_q(const float* __restrict__ lsg, const float* __restrict__ lsb) {
    int row = blockIdx.x;  // b*K+s
    int d = threadIdx.x;   // 0..63
    __shared__ float sh[64];
    __shared__ float red[2], red2[2];
    float v = g_slots[row * 64 + d];
    float s1 = v;
#pragma unroll
    for (int o = 16; o > 0; o >>= 1) s1 += __shfl_xor_sync(0xffffffffu, s1, o);
    if ((d & 31) == 0) red[d >> 5] = s1;
    __syncthreads();
    float mean = (red[0] + red[1]) * (1.f / 64.f);
    float dv = v - mean;
    float s2 = dv * dv;
#pragma unroll
    for (int o = 16; o > 0; o >>= 1) s2 += __shfl_xor_sync(0xffffffffu, s2, o);
    if ((d & 31) == 0) red2[d >> 5] = s2;
    __syncthreads();
    float var = (red2[0] + red2[1]) * (1.f / 64.f);
    float rstd = rsqrtf(var + 1e-5f);
    sh[d] = dv * rstd * lsg[d] + lsb[d];
    __syncthreads();
    float acc = 0.f;
#pragma unroll 8
    for (int e = 0; e < 64; e++) acc += sh[e] * g_WqT[e * 64 + d];
    g_q[row * 64 + d] = acc;
    g_upd[row * 64 + d] = 0.f;
    if (d == 0) g_S[row] = 0.f;
}

// ---------------- dots + softmax(slots) + eps + S + unnormalized updates ----------------
__global__ void __launch_bounds__(256) k_attn(float* __restrict__ out_attn, int last) {
    __shared__ float sq[Kc * Dc];  // 512 floats
    int t = threadIdx.x;
    int b = blockIdx.x >> 4;
    int tile = blockIdx.x & 15;
    sq[t] = g_q[b * 512 + t];
    sq[t + 256] = g_q[b * 512 + 256 + t];
    __syncthreads();

    int p = tile * 256 + t;  // pixel in batch
    const float* kTb = g_kT + (size_t)b * Dc * Pc + p;
    const ull* q2 = (const ull*)sq;  // [8][32] packed pairs

    ull acc[8];
#pragma unroll
    for (int s = 0; s < 8; s++) acc[s] = 0ULL;
#pragma unroll 8
    for (int dp = 0; dp < 32; dp++) {
        float k0 = __ldg(kTb + (size_t)(2 * dp) * Pc);
        float k1v = __ldg(kTb + (size_t)(2 * dp + 1) * Pc);
        ull kk = pack2(k0, k1v);
#pragma unroll
        for (int s = 0; s < 8; s++) acc[s] = fma2(kk, q2[s * 32 + dp], acc[s]);
    }

    float attn[8];
    float mx = -1e30f;
#pragma unroll
    for (int s = 0; s < 8; s++) {
        float2 r = unpack2(acc[s]);
        attn[s] = (r.x + r.y) * 0.125f;  // SCALE = D^-0.5
        mx = fmaxf(mx, attn[s]);
    }
    float sum = 0.f;
#pragma unroll
    for (int s = 0; s < 8; s++) { attn[s] = __expf(attn[s] - mx); sum += attn[s]; }
    float inv = 1.f / sum;
#pragma unroll
    for (int s = 0; s < 8; s++) attn[s] = attn[s] * inv + 1e-8f;

    if (last) {
        float* ao = out_attn + (size_t)b * Kc * Pc + p;
#pragma unroll
        for (int s = 0; s < 8; s++) ao[(size_t)s * Pc] = attn[s];
    }

    int lane = t & 31;
    // per-(b,s) pixel-sum S via warp butterfly + one atomic
#pragma unroll
    for (int s = 0; s < 8; s++) {
        float v = attn[s];
#pragma unroll
        for (int o = 16; o > 0; o >>= 1) v += __shfl_xor_sync(0xffffffffu, v, o);
        if (lane == 0) atomicAdd(&g_S[b * Kc + s], v);
    }

    // updates: rank-8 accumulation; attn broadcast via shfl, v coalesced
    int p0 = p & ~31;
    const ull* vb = (const ull*)(g_v + ((size_t)b * Pc + p0) * Dc) + lane;
    ull ua[8];
#pragma unroll
    for (int s = 0; s < 8; s++) ua[s] = 0ULL;
#pragma unroll 8
    for (int i = 0; i < 32; i++) {
        ull v2 = __ldg(vb + i * 32);
#pragma unroll
        for (int s = 0; s < 8; s++) {
            float a = __shfl_sync(0xffffffffu, attn[s], i);
            ua[s] = fma2(pack2(a, a), v2, ua[s]);
        }
    }
#pragma unroll
    for (int s = 0; s < 8; s++) {
        float2 r = unpack2(ua[s]);
        float* up = &g_upd[(b * Kc + s) * Dc + 2 * lane];
        atomicAdd(up, r.x);
        atomicAdd(up + 1, r.y);
    }
}

// ---------------- GRU cell + LN + FF + residual ----------------
__global__ void k_gru(const float* __restrict__ bih, const float* __restrict__ bhh,
                      const float* __restrict__ ffg, const float* __restrict__ ffb,
                      const float* __restrict__ fb1, const float* __restrict__ fb2,
                      float* __restrict__ out_slots, int last) {
    int row = blockIdx.x;  // b*K+s
    int d = threadIdx.x;   // 0..63
    __shared__ float su[64], sp[64], sf[64], sr1[128];
    __shared__ float red[2], red2[2];

    float S = g_S[row];
    float u = g_upd[row * 64 + d] / S;
    float hp = g_slots[row * 64 + d];
    su[d] = u;
    sp[d] = hp;
    __syncthreads();

    float gir = bih[d], giz = bih[64 + d], gin = bih[128 + d];
    float ghr = bhh[d], ghz = bhh[64 + d], ghn = bhh[128 + d];
#pragma unroll 4
    for (int e = 0; e < 64; e++) {
        float ue = su[e], he = sp[e];
        const float* wi = g_WihT + e * 192 + d;
        const float* wh = g_WhhT + e * 192 + d;
        gir += ue * wi[0];
        giz += ue * wi[64];
        gin += ue * wi[128];
        ghr += he * wh[0];
        ghz += he * wh[64];
        ghn += he * wh[128];
    }
    float r = 1.f / (1.f + expf(-(gir + ghr)));
    float z = 1.f / (1.f + expf(-(giz + ghz)));
    float n = tanhf(gin + r * ghn);
    float h = (1.f - z) * n + z * hp;

    // LayerNorm(h)
    float s1 = h;
#pragma unroll
    for (int o = 16; o > 0; o >>= 1) s1 += __shfl_xor_sync(0xffffffffu, s1, o);
    if ((d & 31) == 0) red[d >> 5] = s1;
    __syncthreads();
    float mean = (red[0] + red[1]) * (1.f / 64.f);
    float dv = h - mean;
    float s2 = dv * dv;
#pragma unroll
    for (int o = 16; o > 0; o >>= 1) s2 += __shfl_xor_sync(0xffffffffu, s2, o);
    if ((d & 31) == 0) red2[d >> 5] = s2;
    __syncthreads();
    float var = (red2[0] + red2[1]) * (1.f / 64.f);
    float rstd = rsqrtf(var + 1e-5f);
    sf[d] = dv * rstd * ffg[d] + ffb[d];
    __syncthreads();

    // FF layer 1 (+ReLU)
    float a0 = fb1[d], a1 = fb1[64 + d];
#pragma unroll 8
    for (int e = 0; e < 64; e++) {
        float f = sf[e];
        a0 += f * g_W1T[e * 128 + d];
        a1 += f * g_W1T[e * 128 + 64 + d];
    }
    sr1[d] = fmaxf(a0, 0.f);
    sr1[64 + d] = fmaxf(a1, 0.f);
    __syncthreads();

    // FF layer 2 + residual
    float o = fb2[d];
#pragma unroll 8
    for (int j = 0; j < 128; j++) o += sr1[j] * g_W2T[j * 64 + d];
    float ns = h + o;
    g_slots[row * 64 + d] = ns;
    if (last) out_slots[row * 64 + d] = ns;
}

// ---------------- final attn normalization over pixels ----------------
__global__ void k_scale(float* __restrict__ out_attn) {
    size_t i = (size_t)blockIdx.x * 256 + threadIdx.x;  // < B*K*P
    int row = (int)(i >> 12);
    out_attn[i] = out_attn[i] / g_S[row];
}

// ---------------- launch ----------------
extern "C" void kernel_launch(void* const* d_in, const int* in_sizes, int n_in,
                              void* d_out, int out_size) {
    const float* x = (const float*)d_in[0];
    const float* noise = (const float*)d_in[1];
    const float* mu = (const float*)d_in[2];
    const float* sigma = (const float*)d_in[3];
    const float* Wq = (const float*)d_in[4];
    const float* Wk = (const float*)d_in[5];
    const float* Wv = (const float*)d_in[6];
    const float* Wih = (const float*)d_in[7];
    const float* Whh = (const float*)d_in[8];
    const float* bih = (const float*)d_in[9];
    const float* bhh = (const float*)d_in[10];
    const float* ling = (const float*)d_in[11];
    const float* linb = (const float*)d_in[12];
    const float* lsg = (const float*)d_in[13];
    const float* lsb = (const float*)d_in[14];
    const float* ffg = (const float*)d_in[15];
    const float* ffb = (const float*)d_in[16];
    const float* W1 = (const float*)d_in[17];
    const float* fb1 = (const float*)d_in[18];
    const float* W2 = (const float*)d_in[19];
    const float* fb2 = (const float*)d_in[20];

    float* out = (float*)d_out;
    float* out_slots = out;                     // [B,K,D]
    float* out_attn = out + Bc * Kc * Dc;       // [B,K,P]

    k_init<<<256, 256>>>(noise, mu, sigma, Wq, Wih, Whh, W1, W2);
    k_proj<<<(Bc * Pc) / 256, 256>>>(x, Wk, Wv, ling, linb);
    for (int it = 0; it < ITERS_C; it++) {
        int last = (it == ITERS_C - 1) ? 1 : 0;
        k_q<<<Bc * Kc, 64>>>(lsg, lsb);
        k_attn<<<(Bc * Pc) / 256, 256>>>(out_attn, last);
        k_gru<<<Bc * Kc, 64>>>(bih, bhh, ffg, ffb, fb1, fb2, out_slots, last);
    }
    k_scale<<<(Bc * Kc * Pc) / 256, 256>>>(out_attn);
}

// round 3
// speedup vs baseline: 1.2621x; 1.2621x over previous
#include <cuda_runtime.h>
#include <cuda_bf16.h>
#include <math.h>

#define Bc 128
#define Pc 4096
#define Fc 32
#define Kc 8
#define Dc 64
#define ITERS_C 2

typedef unsigned long long ull;

// ---------------- scratch (static __device__, no runtime alloc) ----------------
__device__ ull g_kq[(size_t)Bc * 16 * Pc];     // K bf16 quads: [B][dquad 0..15][P], quad q = d{4q..4q+3}
__device__ ull g_vq[(size_t)Bc * Pc * 16];     // V bf16 quads: [B][P][dquad 0..15]
__device__ float g_slots[Bc * Kc * Dc];
__device__ float g_q[Bc * Kc * Dc];
__device__ float g_upd[Bc * Kc * Dc];
__device__ float g_S[Bc * Kc];
__device__ float g_WqT[Dc * Dc];               // [e][d]
__device__ float g_WihT[Dc * 3 * Dc];          // [e][j], stride 192
__device__ float g_WhhT[Dc * 3 * Dc];          // [e][j], stride 192
__device__ float g_W1T[Dc * 2 * Dc];           // [e][j], stride 128
__device__ float g_W2T[2 * Dc * Dc];           // [j][d], stride 64

// ---------------- packed helpers ----------------
__device__ __forceinline__ ull fma2(ull a, ull b, ull c) {
    ull d;
    asm("fma.rn.f32x2 %0, %1, %2, %3;" : "=l"(d) : "l"(a), "l"(b), "l"(c));
    return d;
}
__device__ __forceinline__ ull pack2(float x, float y) {
    ull r;
    asm("mov.b64 %0, {%1, %2};" : "=l"(r) : "f"(x), "f"(y));
    return r;
}
__device__ __forceinline__ float2 unpack2(ull v) {
    float2 r;
    asm("mov.b64 {%0, %1}, %2;" : "=f"(r.x), "=f"(r.y) : "l"(v));
    return r;
}
__device__ __forceinline__ unsigned bf2_of(float lo, float hi) {
    unsigned r;
    asm("cvt.rn.bf16x2.f32 %0, %1, %2;" : "=r"(r) : "f"(hi), "f"(lo));
    return r;
}
__device__ __forceinline__ ull packu(unsigned lo, unsigned hi) {
    ull r;
    asm("mov.b64 %0, {%1, %2};" : "=l"(r) : "r"(lo), "r"(hi));
    return r;
}
__device__ __forceinline__ void unpacku(ull v, unsigned& lo, unsigned& hi) {
    asm("mov.b64 {%0, %1}, %2;" : "=r"(lo), "=r"(hi) : "l"(v));
}
__device__ __forceinline__ float bflo(unsigned u) { return __uint_as_float(u << 16); }
__device__ __forceinline__ float bfhi(unsigned u) { return __uint_as_float(u & 0xffff0000u); }

// ---------------- init: slots init + weight transposes ----------------
__global__ void k_init(const float* __restrict__ noise, const float* __restrict__ mu,
                       const float* __restrict__ sigma, const float* __restrict__ Wq,
                       const float* __restrict__ Wih, const float* __restrict__ Whh,
                       const float* __restrict__ W1, const float* __restrict__ W2) {
    int i = blockIdx.x * blockDim.x + threadIdx.x;  // 0..65535
    if (i < Bc * Kc * Dc) {
        int d = i & 63;
        g_slots[i] = mu[d] + fabsf(sigma[d]) * noise[i];
    }
    if (i < Dc * Dc) {  // Wq [64,64] -> [e][d]
        g_WqT[(i & 63) * Dc + (i >> 6)] = Wq[i];
    }
    if (i < 3 * Dc * Dc) {  // [192,64] -> [e][j]
        int j = i >> 6, e = i & 63;
        g_WihT[e * 192 + j] = Wih[i];
        g_WhhT[e * 192 + j] = Whh[i];
    }
    if (i < 2 * Dc * Dc) {  // ff_W1 [128,64] -> [e][j]
        int j = i >> 6, e = i & 63;
        g_W1T[e * 128 + j] = W1[i];
    }
    if (i < 2 * Dc * Dc) {  // ff_W2 [64,128] -> [j][d]
        int dd = i >> 7, j = i & 127;
        g_W2T[j * 64 + dd] = W2[i];
    }
}

// ---------------- LayerNorm(x) + K/V projection (bf16 outputs) ----------------
__global__ void __launch_bounds__(256) k_proj(const float* __restrict__ x,
                                              const float* __restrict__ Wk,
                                              const float* __restrict__ Wv,
                                              const float* __restrict__ lg,
                                              const float* __restrict__ lb) {
    __shared__ float sW[Fc][128];  // [f][0..63]=WkT, [f][64..127]=WvT
    __shared__ float sg[Fc], sb[Fc];
    int t = threadIdx.x;
    for (int i = t; i < Dc * Fc; i += 256) {
        int d = i >> 5, f = i & 31;
        sW[f][d] = Wk[i];
        sW[f][64 + d] = Wv[i];
    }
    if (t < Fc) { sg[t] = lg[t]; sb[t] = lb[t]; }
    __syncthreads();

    size_t gp = (size_t)blockIdx.x * 256 + t;  // global pixel in [0, B*P)
    int b = (int)(gp >> 12);
    int p = (int)(gp & 4095);

    const float4* xr4 = (const float4*)(x + gp * Fc);
    float xv[32];
#pragma unroll
    for (int j = 0; j < 8; j++) {
        float4 q = xr4[j];
        xv[4 * j] = q.x; xv[4 * j + 1] = q.y; xv[4 * j + 2] = q.z; xv[4 * j + 3] = q.w;
    }
    float m = 0.f;
#pragma unroll
    for (int f = 0; f < 32; f++) m += xv[f];
    m *= (1.f / 32.f);
    float var = 0.f;
#pragma unroll
    for (int f = 0; f < 32; f++) { float dv = xv[f] - m; var += dv * dv; }
    var *= (1.f / 32.f);
    float rstd = rsqrtf(var + 1e-5f);
#pragma unroll
    for (int f = 0; f < 32; f++) xv[f] = (xv[f] - m) * rstd * sg[f] + sb[f];

#pragma unroll
    for (int c = 0; c < 4; c++) {  // 4 chunks of 32 outputs (16 d-pairs)
        ull acc[16];
#pragma unroll
        for (int j = 0; j < 16; j++) acc[j] = 0ULL;
#pragma unroll 4
        for (int f = 0; f < 32; f++) {
            ull xx = pack2(xv[f], xv[f]);
            const ull* w2 = (const ull*)&sW[f][32 * c];
#pragma unroll
            for (int j = 0; j < 16; j++) acc[j] = fma2(xx, w2[j], acc[j]);
        }
        if (c < 2) {  // K -> bf16 quads [B][16][P]
#pragma unroll
            for (int j = 0; j < 16; j += 2) {
                float2 r0 = unpack2(acc[j]);
                float2 r1 = unpack2(acc[j + 1]);
                unsigned b0 = bf2_of(r0.x, r0.y);
                unsigned b1 = bf2_of(r1.x, r1.y);
                int q = 8 * c + (j >> 1);
                g_kq[((size_t)b * 16 + q) * Pc + p] = packu(b0, b1);
            }
        } else {  // V -> bf16 quads [B][P][16]
#pragma unroll
            for (int j = 0; j < 16; j += 2) {
                float2 r0 = unpack2(acc[j]);
                float2 r1 = unpack2(acc[j + 1]);
                unsigned b0 = bf2_of(r0.x, r0.y);
                unsigned b1 = bf2_of(r1.x, r1.y);
                int q = 8 * (c - 2) + (j >> 1);
                g_vq[gp * 16 + q] = packu(b0, b1);
            }
        }
    }
}

// ---------------- q = LN(slots) @ Wq^T; zero S and upd ----------------
__global__ void k_q(const float* __restrict__ lsg, const float* __restrict__ lsb) {
    int row = blockIdx.x;  // b*K+s
    int d = threadIdx.x;   // 0..63
    __shared__ float sh[64];
    __shared__ float red[2], red2[2];
    float v = g_slots[row * 64 + d];
    float s1 = v;
#pragma unroll
    for (int o = 16; o > 0; o >>= 1) s1 += __shfl_xor_sync(0xffffffffu, s1, o);
    if ((d & 31) == 0) red[d >> 5] = s1;
    __syncthreads();
    float mean = (red[0] + red[1]) * (1.f / 64.f);
    float dv = v - mean;
    float s2 = dv * dv;
#pragma unroll
    for (int o = 16; o > 0; o >>= 1) s2 += __shfl_xor_sync(0xffffffffu, s2, o);
    if ((d & 31) == 0) red2[d >> 5] = s2;
    __syncthreads();
    float var = (red2[0] + red2[1]) * (1.f / 64.f);
    float rstd = rsqrtf(var + 1e-5f);
    sh[d] = dv * rstd * lsg[d] + lsb[d];
    __syncthreads();
    float acc = 0.f;
#pragma unroll 8
    for (int e = 0; e < 64; e++) acc += sh[e] * g_WqT[e * 64 + d];
    g_q[row * 64 + d] = acc;
    g_upd[row * 64 + d] = 0.f;
    if (d == 0) g_S[row] = 0.f;
}

// ---------------- dots + softmax(slots) + eps + S + unnormalized updates ----------------
__global__ void __launch_bounds__(256) k_attn(float* __restrict__ out_attn, int last) {
    __shared__ ull sq[256];        // q pairs: flat [s*32 + dpair]
    __shared__ ull sa[8][256];     // attn duplicated as (a,a) per (slot, tile-pixel)
    __shared__ float supd[512];    // block-local update accumulator [s][64]
    int t = threadIdx.x;
    int b = blockIdx.x >> 4;
    int tile = blockIdx.x & 15;
    {
        float q0 = g_q[b * 512 + 2 * t];
        float q1 = g_q[b * 512 + 2 * t + 1];
        sq[t] = pack2(q0, q1);
    }
    supd[t] = 0.f;
    supd[t + 256] = 0.f;
    __syncthreads();

    int p = tile * 256 + t;  // pixel in batch
    const ull* kb = g_kq + (size_t)b * 16 * Pc + p;

    // dots: 16 LDG.64 of bf16 quads, fp32 accumulation
    ull acc[8];
#pragma unroll
    for (int s = 0; s < 8; s++) acc[s] = 0ULL;
#pragma unroll
    for (int q = 0; q < 16; q++) {
        ull kv = __ldg(kb + (size_t)q * Pc);
        unsigned lo, hi;
        unpacku(kv, lo, hi);
        ull kkA = pack2(bflo(lo), bfhi(lo));  // d = 4q, 4q+1
        ull kkB = pack2(bflo(hi), bfhi(hi));  // d = 4q+2, 4q+3
#pragma unroll
        for (int s = 0; s < 8; s++) {
            acc[s] = fma2(kkA, sq[s * 32 + 2 * q], acc[s]);
            acc[s] = fma2(kkB, sq[s * 32 + 2 * q + 1], acc[s]);
        }
    }

    float attn[8];
    float mx = -1e30f;
#pragma unroll
    for (int s = 0; s < 8; s++) {
        float2 r = unpack2(acc[s]);
        attn[s] = (r.x + r.y) * 0.125f;  // SCALE = D^-0.5
        mx = fmaxf(mx, attn[s]);
    }
    float sum = 0.f;
#pragma unroll
    for (int s = 0; s < 8; s++) { attn[s] = __expf(attn[s] - mx); sum += attn[s]; }
    float inv = 1.f / sum;
#pragma unroll
    for (int s = 0; s < 8; s++) attn[s] = attn[s] * inv + 1e-8f;

#pragma unroll
    for (int s = 0; s < 8; s++) sa[s][t] = pack2(attn[s], attn[s]);

    if (last) {
        float* ao = out_attn + (size_t)b * Kc * Pc + p;
#pragma unroll
        for (int s = 0; s < 8; s++) ao[(size_t)s * Pc] = attn[s];
    }
    __syncthreads();

    int w = t >> 5, lane = t & 31;

    // S: warp w reduces slot w over the tile (reads from smem, one atomic per warp)
    {
        float s2 = 0.f;
#pragma unroll
        for (int j = 0; j < 8; j++) s2 += unpack2(sa[w][lane + 32 * j]).x;
#pragma unroll
        for (int o = 16; o > 0; o >>= 1) s2 += __shfl_xor_sync(0xffffffffu, s2, o);
        if (lane == 0) atomicAdd(&g_S[b * Kc + w], s2);
    }

    // updates: rank-8 accumulation; attn via uniform LDS.64 broadcast, v bf16 coalesced
    int p0 = tile * 256 + w * 32;
    const unsigned* vb = (const unsigned*)g_vq + ((size_t)b * Pc + p0) * 32 + lane;
    ull ua[8];
#pragma unroll
    for (int s = 0; s < 8; s++) ua[s] = 0ULL;
#pragma unroll 8
    for (int i = 0; i < 32; i++) {
        unsigned u = __ldg(vb + i * 32);        // bf162 for d = 2*lane, 2*lane+1
        ull v2 = pack2(bflo(u), bfhi(u));
#pragma unroll
        for (int s = 0; s < 8; s++) ua[s] = fma2(sa[s][w * 32 + i], v2, ua[s]);
    }
#pragma unroll
    for (int s = 0; s < 8; s++) {
        float2 r = unpack2(ua[s]);
        atomicAdd(&supd[s * 64 + 2 * lane], r.x);
        atomicAdd(&supd[s * 64 + 2 * lane + 1], r.y);
    }
    __syncthreads();
    atomicAdd(&g_upd[b * 512 + t], supd[t]);
    atomicAdd(&g_upd[b * 512 + t + 256], supd[t + 256]);
}

// ---------------- GRU cell + LN + FF + residual ----------------
__global__ void k_gru(const float* __restrict__ bih, const float* __restrict__ bhh,
                      const float* __restrict__ ffg, const float* __restrict__ ffb,
                      const float* __restrict__ fb1, const float* __restrict__ fb2,
                      float* __restrict__ out_slots, int last) {
    int row = blockIdx.x;  // b*K+s
    int d = threadIdx.x;   // 0..63
    __shared__ float su[64], sp[64], sf[64], sr1[128];
    __shared__ float red[2], red2[2];

    float S = g_S[row];
    float u = g_upd[row * 64 + d] / S;
    float hp = g_slots[row * 64 + d];
    su[d] = u;
    sp[d] = hp;
    __syncthreads();

    float gir = bih[d], giz = bih[64 + d], gin = bih[128 + d];
    float ghr = bhh[d], ghz = bhh[64 + d], ghn = bhh[128 + d];
#pragma unroll 4
    for (int e = 0; e < 64; e++) {
        float ue = su[e], he = sp[e];
        const float* wi = g_WihT + e * 192 + d;
        const float* wh = g_WhhT + e * 192 + d;
        gir += ue * wi[0];
        giz += ue * wi[64];
        gin += ue * wi[128];
        ghr += he * wh[0];
        ghz += he * wh[64];
        ghn += he * wh[128];
    }
    float r = 1.f / (1.f + expf(-(gir + ghr)));
    float z = 1.f / (1.f + expf(-(giz + ghz)));
    float n = tanhf(gin + r * ghn);
    float h = (1.f - z) * n + z * hp;

    // LayerNorm(h)
    float s1 = h;
#pragma unroll
    for (int o = 16; o > 0; o >>= 1) s1 += __shfl_xor_sync(0xffffffffu, s1, o);
    if ((d & 31) == 0) red[d >> 5] = s1;
    __syncthreads();
    float mean = (red[0] + red[1]) * (1.f / 64.f);
    float dv = h - mean;
    float s2 = dv * dv;
#pragma unroll
    for (int o = 16; o > 0; o >>= 1) s2 += __shfl_xor_sync(0xffffffffu, s2, o);
    if ((d & 31) == 0) red2[d >> 5] = s2;
    __syncthreads();
    float var = (red2[0] + red2[1]) * (1.f / 64.f);
    float rstd = rsqrtf(var + 1e-5f);
    sf[d] = dv * rstd * ffg[d] + ffb[d];
    __syncthreads();

    // FF layer 1 (+ReLU)
    float a0 = fb1[d], a1 = fb1[64 + d];
#pragma unroll 8
    for (int e = 0; e < 64; e++) {
        float f = sf[e];
        a0 += f * g_W1T[e * 128 + d];
        a1 += f * g_W1T[e * 128 + 64 + d];
    }
    sr1[d] = fmaxf(a0, 0.f);
    sr1[64 + d] = fmaxf(a1, 0.f);
    __syncthreads();

    // FF layer 2 + residual
    float o = fb2[d];
#pragma unroll 8
    for (int j = 0; j < 128; j++) o += sr1[j] * g_W2T[j * 64 + d];
    float ns = h + o;
    g_slots[row * 64 + d] = ns;
    if (last) out_slots[row * 64 + d] = ns;
}

// ---------------- final attn normalization over pixels ----------------
__global__ void k_scale(float* __restrict__ out_attn) {
    size_t i = (size_t)blockIdx.x * 256 + threadIdx.x;  // < B*K*P
    int row = (int)(i >> 12);
    out_attn[i] = out_attn[i] / g_S[row];
}

// ---------------- launch ----------------
extern "C" void kernel_launch(void* const* d_in, const int* in_sizes, int n_in,
                              void* d_out, int out_size) {
    const float* x = (const float*)d_in[0];
    const float* noise = (const float*)d_in[1];
    const float* mu = (const float*)d_in[2];
    const float* sigma = (const float*)d_in[3];
    const float* Wq = (const float*)d_in[4];
    const float* Wk = (const float*)d_in[5];
    const float* Wv = (const float*)d_in[6];
    const float* Wih = (const float*)d_in[7];
    const float* Whh = (const float*)d_in[8];
    const float* bih = (const float*)d_in[9];
    const float* bhh = (const float*)d_in[10];
    const float* ling = (const float*)d_in[11];
    const float* linb = (const float*)d_in[12];
    const float* lsg = (const float*)d_in[13];
    const float* lsb = (const float*)d_in[14];
    const float* ffg = (const float*)d_in[15];
    const float* ffb = (const float*)d_in[16];
    const float* W1 = (const float*)d_in[17];
    const float* fb1 = (const float*)d_in[18];
    const float* W2 = (const float*)d_in[19];
    const float* fb2 = (const float*)d_in[20];

    float* out = (float*)d_out;
    float* out_slots = out;                     // [B,K,D]
    float* out_attn = out + Bc * Kc * Dc;       // [B,K,P]

    k_init<<<256, 256>>>(noise, mu, sigma, Wq, Wih, Whh, W1, W2);
    k_proj<<<(Bc * Pc) / 256, 256>>>(x, Wk, Wv, ling, linb);
    for (int it = 0; it < ITERS_C; it++) {
        int last = (it == ITERS_C - 1) ? 1 : 0;
        k_q<<<Bc * Kc, 64>>>(lsg, lsb);
        k_attn<<<(Bc * Pc) / 256, 256>>>(out_attn, last);
        k_gru<<<Bc * Kc, 64>>>(bih, bhh, ffg, ffb, fb1, fb2, out_slots, last);
    }
    k_scale<<<(Bc * Kc * Pc) / 256, 256>>>(out_attn);
}

// round 6
// speedup vs baseline: 1.3551x; 1.0737x over previous
#include <cuda_runtime.h>
#include <cuda_bf16.h>
#include <math.h>

#define Bc 128
#define Pc 4096
#define Fc 32
#define Kc 8
#define Dc 64
#define ITERS_C 2

typedef unsigned long long ull;

// ---------------- scratch (static __device__, no runtime alloc) ----------------
__device__ ull g_kq[(size_t)Bc * 16 * Pc];     // K bf16 quads: [B][dquad 0..15][P], quad q = d{4q..4q+3}
__device__ ull g_vq[(size_t)Bc * Pc * 16];     // V bf16 quads: [B][P][dquad 0..15]
__device__ float g_slots[Bc * Kc * Dc];
__device__ float g_q[Bc * Kc * Dc];
__device__ float g_upd[Bc * Kc * Dc];
__device__ float g_S[Bc * Kc];
__device__ float g_WqT[Dc * Dc];               // [e][d]
__device__ float g_WihT[Dc * 3 * Dc];          // [e][j], stride 192
__device__ float g_WhhT[Dc * 3 * Dc];          // [e][j], stride 192
__device__ float g_W1T[Dc * 2 * Dc];           // [e][j], stride 128
__device__ float g_W2T[2 * Dc * Dc];           // [j][d], stride 64

// ---------------- packed helpers ----------------
__device__ __forceinline__ ull fma2(ull a, ull b, ull c) {
    ull d;
    asm("fma.rn.f32x2 %0, %1, %2, %3;" : "=l"(d) : "l"(a), "l"(b), "l"(c));
    return d;
}
__device__ __forceinline__ ull pack2(float x, float y) {
    ull r;
    asm("mov.b64 %0, {%1, %2};" : "=l"(r) : "f"(x), "f"(y));
    return r;
}
__device__ __forceinline__ float2 unpack2(ull v) {
    float2 r;
    asm("mov.b64 {%0, %1}, %2;" : "=f"(r.x), "=f"(r.y) : "l"(v));
    return r;
}
__device__ __forceinline__ unsigned bf2_of(float lo, float hi) {
    unsigned r;
    asm("cvt.rn.bf16x2.f32 %0, %1, %2;" : "=r"(r) : "f"(hi), "f"(lo));
    return r;
}
__device__ __forceinline__ ull packu(unsigned lo, unsigned hi) {
    ull r;
    asm("mov.b64 %0, {%1, %2};" : "=l"(r) : "r"(lo), "r"(hi));
    return r;
}
__device__ __forceinline__ void unpacku(ull v, unsigned& lo, unsigned& hi) {
    asm("mov.b64 {%0, %1}, %2;" : "=r"(lo), "=r"(hi) : "l"(v));
}
__device__ __forceinline__ float bflo(unsigned u) { return __uint_as_float(u << 16); }
__device__ __forceinline__ float bfhi(unsigned u) { return __uint_as_float(u & 0xffff0000u); }

// ---------------- init: slots init + weight transposes ----------------
__global__ void k_init(const float* __restrict__ noise, const float* __restrict__ mu,
                       const float* __restrict__ sigma, const float* __restrict__ Wq,
                       const float* __restrict__ Wih, const float* __restrict__ Whh,
                       const float* __restrict__ W1, const float* __restrict__ W2) {
    int i = blockIdx.x * blockDim.x + threadIdx.x;  // 0..65535
    if (i < Bc * Kc * Dc) {
        int d = i & 63;
        g_slots[i] = mu[d] + fabsf(sigma[d]) * noise[i];
    }
    if (i < Dc * Dc) {  // Wq [64,64] -> [e][d]
        g_WqT[(i & 63) * Dc + (i >> 6)] = Wq[i];
    }
    if (i < 3 * Dc * Dc) {  // [192,64] -> [e][j]
        int j = i >> 6, e = i & 63;
        g_WihT[e * 192 + j] = Wih[i];
        g_WhhT[e * 192 + j] = Whh[i];
    }
    if (i < 2 * Dc * Dc) {  // ff_W1 [128,64] -> [e][j]
        int j = i >> 6, e = i & 63;
        g_W1T[e * 128 + j] = W1[i];
    }
    if (i < 2 * Dc * Dc) {  // ff_W2 [64,128] -> [j][d]
        int dd = i >> 7, j = i & 127;
        g_W2T[j * 64 + dd] = W2[i];
    }
}

// ---------------- LayerNorm(x) + K/V projection (bf16 outputs) ----------------
// dynamic smem layout:
//   [0, 16384)         sW[32][128]   (weights: [f][0..63]=WkT, [f][64..127]=WvT)
//   [16384, 16512)     sg[32]
//   [16512, 16640)     sb[32]
//   [16640, 53504)     sv[256][18] ull  (V staging, padded rows for banks, 16B-aligned)
#define PROJ_SMEM 53504
__global__ void __launch_bounds__(256) k_proj(const float* __restrict__ x,
                                              const float* __restrict__ Wk,
                                              const float* __restrict__ Wv,
                                              const float* __restrict__ lg,
                                              const float* __restrict__ lb) {
    extern __shared__ char dsm[];
    float (*sW)[128] = (float(*)[128])dsm;
    float* sg = (float*)(dsm + 16384);
    float* sb = (float*)(dsm + 16512);
    ull* sv = (ull*)(dsm + 16640);

    int t = threadIdx.x;
    for (int i = t; i < Dc * Fc; i += 256) {
        int d = i >> 5, f = i & 31;
        sW[f][d] = Wk[i];
        sW[f][64 + d] = Wv[i];
    }
    if (t < Fc) { sg[t] = lg[t]; sb[t] = lb[t]; }
    __syncthreads();

    size_t gpbase = (size_t)blockIdx.x * 256;
    size_t gp = gpbase + t;  // global pixel in [0, B*P)
    int b = (int)(gp >> 12);
    int p = (int)(gp & 4095);

    const float4* xr4 = (const float4*)(x + gp * Fc);
    float xv[32];
#pragma unroll
    for (int j = 0; j < 8; j++) {
        float4 q = xr4[j];
        xv[4 * j] = q.x; xv[4 * j + 1] = q.y; xv[4 * j + 2] = q.z; xv[4 * j + 3] = q.w;
    }
    float m = 0.f;
#pragma unroll
    for (int f = 0; f < 32; f++) m += xv[f];
    m *= (1.f / 32.f);
    float var = 0.f;
#pragma unroll
    for (int f = 0; f < 32; f++) { float dv = xv[f] - m; var += dv * dv; }
    var *= (1.f / 32.f);
    float rstd = rsqrtf(var + 1e-5f);
#pragma unroll
    for (int f = 0; f < 32; f++) xv[f] = (xv[f] - m) * rstd * sg[f] + sb[f];

#pragma unroll
    for (int c = 0; c < 4; c++) {  // 4 chunks of 32 outputs (16 d-pairs)
        ull acc[16];
#pragma unroll
        for (int j = 0; j < 16; j++) acc[j] = 0ULL;
#pragma unroll 4
        for (int f = 0; f < 32; f++) {
            ull xx = pack2(xv[f], xv[f]);
            const ulonglong2* w2 = (const ulonglong2*)&sW[f][32 * c];  // 8 x LDS.128
#pragma unroll
            for (int j = 0; j < 8; j++) {
                ulonglong2 wp = w2[j];
                acc[2 * j] = fma2(xx, wp.x, acc[2 * j]);
                acc[2 * j + 1] = fma2(xx, wp.y, acc[2 * j + 1]);
            }
        }
        if (c < 2) {  // K -> bf16 quads [B][16][P] (coalesced over p)
#pragma unroll
            for (int j = 0; j < 16; j += 2) {
                float2 r0 = unpack2(acc[j]);
                float2 r1 = unpack2(acc[j + 1]);
                unsigned b0 = bf2_of(r0.x, r0.y);
                unsigned b1 = bf2_of(r1.x, r1.y);
                int q = 8 * c + (j >> 1);
                g_kq[((size_t)b * 16 + q) * Pc + p] = packu(b0, b1);
            }
        } else {  // V -> stage quads in smem (coalesced flush below)
            int qb = (c - 2) * 8;  // quad base 0 or 8
#pragma unroll
            for (int j = 0; j < 16; j += 4) {  // 2 quads per iter -> 1 STS.128
                float2 r0 = unpack2(acc[j]);
                float2 r1 = unpack2(acc[j + 1]);
                float2 r2 = unpack2(acc[j + 2]);
                float2 r3 = unpack2(acc[j + 3]);
                ulonglong2 qq;
                qq.x = packu(bf2_of(r0.x, r0.y), bf2_of(r1.x, r1.y));
                qq.y = packu(bf2_of(r2.x, r2.y), bf2_of(r3.x, r3.y));
                *(ulonglong2*)&sv[t * 18 + qb + (j >> 1)] = qq;
            }
        }
    }
    __syncthreads();

    // flush V: 256 px * 16 quads = 2048 ulonglong2, fully coalesced STG.128
    // (FIX vs prior round: cover ALL 16 quads -> 8 iterations, stride 2 quads)
    ull* vout = (ull*)g_vq + gpbase * 16;
#pragma unroll
    for (int k = 0; k < 8; k++) {
        int i = t + 256 * k;          // 0..2047 (ulonglong2 index)
        int px = i >> 3, u = i & 7;   // u = which pair-of-quads (0..7)
        ulonglong2 qq = *(const ulonglong2*)&sv[px * 18 + 2 * u];
        *(ulonglong2*)&vout[(size_t)px * 16 + 2 * u] = qq;
    }
}

// ---------------- q = LN(slots) @ Wq^T; zero S and upd ----------------
__global__ void k_q(const float* __restrict__ lsg, const float* __restrict__ lsb) {
    int row = blockIdx.x;  // b*K+s
    int d = threadIdx.x;   // 0..63
    __shared__ float sh[64];
    __shared__ float red[2], red2[2];
    float v = g_slots[row * 64 + d];
    float s1 = v;
#pragma unroll
    for (int o = 16; o > 0; o >>= 1) s1 += __shfl_xor_sync(0xffffffffu, s1, o);
    if ((d & 31) == 0) red[d >> 5] = s1;
    __syncthreads();
    float mean = (red[0] + red[1]) * (1.f / 64.f);
    float dv = v - mean;
    float s2 = dv * dv;
#pragma unroll
    for (int o = 16; o > 0; o >>= 1) s2 += __shfl_xor_sync(0xffffffffu, s2, o);
    if ((d & 31) == 0) red2[d >> 5] = s2;
    __syncthreads();
    float var = (red2[0] + red2[1]) * (1.f / 64.f);
    float rstd = rsqrtf(var + 1e-5f);
    sh[d] = dv * rstd * lsg[d] + lsb[d];
    __syncthreads();
    float acc = 0.f;
#pragma unroll 8
    for (int e = 0; e < 64; e++) acc += sh[e] * g_WqT[e * 64 + d];
    g_q[row * 64 + d] = acc;
    g_upd[row * 64 + d] = 0.f;
    if (d == 0) g_S[row] = 0.f;
}

// ---------------- dots + softmax(slots) + eps + S + unnormalized updates ----------------
__global__ void __launch_bounds__(256) k_attn(float* __restrict__ out_attn, int last) {
    __shared__ ull sq2[32][8];     // q pairs: [dpair][slot], 2KB, rows 16B-aligned
    __shared__ ull sa[256][10];    // attn (a,a) pairs, pixel-major, pad->10 (20KB, 16B-aligned rows)
    __shared__ float supd[512];    // block-local update accumulator [s][64]
    int t = threadIdx.x;
    int b = blockIdx.x >> 4;
    int tile = blockIdx.x & 15;
    {
        int dp = t >> 3, s = t & 7;
        float q0 = g_q[b * 512 + s * 64 + 2 * dp];
        float q1 = g_q[b * 512 + s * 64 + 2 * dp + 1];
        sq2[dp][s] = pack2(q0, q1);
    }
    supd[t] = 0.f;
    supd[t + 256] = 0.f;
    __syncthreads();

    int p = tile * 256 + t;  // pixel in batch
    const ull* kb = g_kq + (size_t)b * 16 * Pc + p;

    // dots: 16 LDG.64 of bf16 quads, q via LDS.128, fp32 accumulation
    ull acc[8];
#pragma unroll
    for (int s = 0; s < 8; s++) acc[s] = 0ULL;
#pragma unroll
    for (int q = 0; q < 16; q++) {
        ull kv = __ldg(kb + (size_t)q * Pc);
        unsigned lo, hi;
        unpacku(kv, lo, hi);
        ull kkA = pack2(bflo(lo), bfhi(lo));  // d = 4q, 4q+1
        ull kkB = pack2(bflo(hi), bfhi(hi));  // d = 4q+2, 4q+3
        const ulonglong2* qa = (const ulonglong2*)sq2[2 * q];
        const ulonglong2* qb4 = (const ulonglong2*)sq2[2 * q + 1];
#pragma unroll
        for (int j = 0; j < 4; j++) {
            ulonglong2 av = qa[j];
            ulonglong2 bv = qb4[j];
            acc[2 * j] = fma2(kkA, av.x, acc[2 * j]);
            acc[2 * j + 1] = fma2(kkA, av.y, acc[2 * j + 1]);
            acc[2 * j] = fma2(kkB, bv.x, acc[2 * j]);
            acc[2 * j + 1] = fma2(kkB, bv.y, acc[2 * j + 1]);
        }
    }

    float attn[8];
    float mx = -1e30f;
#pragma unroll
    for (int s = 0; s < 8; s++) {
        float2 r = unpack2(acc[s]);
        attn[s] = (r.x + r.y) * 0.125f;  // SCALE = D^-0.5
        mx = fmaxf(mx, attn[s]);
    }
    float sum = 0.f;
#pragma unroll
    for (int s = 0; s < 8; s++) { attn[s] = __expf(attn[s] - mx); sum += attn[s]; }
    float inv = 1.f / sum;
#pragma unroll
    for (int s = 0; s < 8; s++) attn[s] = attn[s] * inv + 1e-8f;

    // write attn pairs pixel-major (vector STS.128)
#pragma unroll
    for (int s = 0; s < 8; s += 2) {
        ulonglong2 aa;
        aa.x = pack2(attn[s], attn[s]);
        aa.y = pack2(attn[s + 1], attn[s + 1]);
        *(ulonglong2*)&sa[t][s] = aa;
    }

    if (last) {
        float* ao = out_attn + (size_t)b * Kc * Pc + p;
#pragma unroll
        for (int s = 0; s < 8; s++) ao[(size_t)s * Pc] = attn[s];
    }
    __syncthreads();

    int w = t >> 5, lane = t & 31;

    // S: warp w reduces slot w over the tile
    {
        float s2 = 0.f;
#pragma unroll
        for (int j = 0; j < 8; j++) s2 += unpack2(sa[lane + 32 * j][w]).x;
#pragma unroll
        for (int o = 16; o > 0; o >>= 1) s2 += __shfl_xor_sync(0xffffffffu, s2, o);
        if (lane == 0) atomicAdd(&g_S[b * Kc + w], s2);
    }

    // updates: rank-8 accumulation; attn via uniform LDS.128, v bf16 coalesced
    int p0 = w * 32;  // pixel group within tile
    const unsigned* vb = (const unsigned*)g_vq + ((size_t)b * Pc + tile * 256 + p0) * 32 + lane;
    ull ua[8];
#pragma unroll
    for (int s = 0; s < 8; s++) ua[s] = 0ULL;
#pragma unroll 8
    for (int i = 0; i < 32; i++) {
        unsigned u = __ldg(vb + i * 32);        // bf162 for d = 2*lane, 2*lane+1
        ull v2 = pack2(bflo(u), bfhi(u));
        const ulonglong2* ap = (const ulonglong2*)sa[p0 + i];
        ulonglong2 a01 = ap[0], a23 = ap[1], a45 = ap[2], a67 = ap[3];
        ua[0] = fma2(a01.x, v2, ua[0]);
        ua[1] = fma2(a01.y, v2, ua[1]);
        ua[2] = fma2(a23.x, v2, ua[2]);
        ua[3] = fma2(a23.y, v2, ua[3]);
        ua[4] = fma2(a45.x, v2, ua[4]);
        ua[5] = fma2(a45.y, v2, ua[5]);
        ua[6] = fma2(a67.x, v2, ua[6]);
        ua[7] = fma2(a67.y, v2, ua[7]);
    }
#pragma unroll
    for (int s = 0; s < 8; s++) {
        float2 r = unpack2(ua[s]);
        atomicAdd(&supd[s * 64 + 2 * lane], r.x);
        atomicAdd(&supd[s * 64 + 2 * lane + 1], r.y);
    }
    __syncthreads();
    atomicAdd(&g_upd[b * 512 + t], supd[t]);
    atomicAdd(&g_upd[b * 512 + t + 256], supd[t + 256]);
}

// ---------------- GRU cell + LN + FF + residual ----------------
__global__ void k_gru(const float* __restrict__ bih, const float* __restrict__ bhh,
                      const float* __restrict__ ffg, const float* __restrict__ ffb,
                      const float* __restrict__ fb1, const float* __restrict__ fb2,
                      float* __restrict__ out_slots, int last) {
    int row = blockIdx.x;  // b*K+s
    int d = threadIdx.x;   // 0..63
    __shared__ float su[64], sp[64], sf[64], sr1[128];
    __shared__ float red[2], red2[2];

    float S = g_S[row];
    float u = g_upd[row * 64 + d] / S;
    float hp = g_slots[row * 64 + d];
    su[d] = u;
    sp[d] = hp;
    __syncthreads();

    float gir = bih[d], giz = bih[64 + d], gin = bih[128 + d];
    float ghr = bhh[d], ghz = bhh[64 + d], ghn = bhh[128 + d];
#pragma unroll 4
    for (int e = 0; e < 64; e++) {
        float ue = su[e], he = sp[e];
        const float* wi = g_WihT + e * 192 + d;
        const float* wh = g_WhhT + e * 192 + d;
        gir += ue * wi[0];
        giz += ue * wi[64];
        gin += ue * wi[128];
        ghr += he * wh[0];
        ghz += he * wh[64];
        ghn += he * wh[128];
    }
    float r = 1.f / (1.f + expf(-(gir + ghr)));
    float z = 1.f / (1.f + expf(-(giz + ghz)));
    float n = tanhf(gin + r * ghn);
    float h = (1.f - z) * n + z * hp;

    // LayerNorm(h)
    float s1 = h;
#pragma unroll
    for (int o = 16; o > 0; o >>= 1) s1 += __shfl_xor_sync(0xffffffffu, s1, o);
    if ((d & 31) == 0) red[d >> 5] = s1;
    __syncthreads();
    float mean = (red[0] + red[1]) * (1.f / 64.f);
    float dv = h - mean;
    float s2 = dv * dv;
#pragma unroll
    for (int o = 16; o > 0; o >>= 1) s2 += __shfl_xor_sync(0xffffffffu, s2, o);
    if ((d & 31) == 0) red2[d >> 5] = s2;
    __syncthreads();
    float var = (red2[0] + red2[1]) * (1.f / 64.f);
    float rstd = rsqrtf(var + 1e-5f);
    sf[d] = dv * rstd * ffg[d] + ffb[d];
    __syncthreads();

    // FF layer 1 (+ReLU)
    float a0 = fb1[d], a1 = fb1[64 + d];
#pragma unroll 8
    for (int e = 0; e < 64; e++) {
        float f = sf[e];
        a0 += f * g_W1T[e * 128 + d];
        a1 += f * g_W1T[e * 128 + 64 + d];
    }
    sr1[d] = fmaxf(a0, 0.f);
    sr1[64 + d] = fmaxf(a1, 0.f);
    __syncthreads();

    // FF layer 2 + residual
    float o = fb2[d];
#pragma unroll 8
    for (int j = 0; j < 128; j++) o += sr1[j] * g_W2T[j * 64 + d];
    float ns = h + o;
    g_slots[row * 64 + d] = ns;
    if (last) out_slots[row * 64 + d] = ns;
}

// ---------------- final attn normalization over pixels (vectorized) ----------------
__global__ void k_scale(float* __restrict__ out_attn) {
    size_t i = (size_t)blockIdx.x * 256 + threadIdx.x;  // float4 index < B*K*P/4
    int row = (int)((i * 4) >> 12);
    float inv = 1.f / g_S[row];
    float4* p4 = (float4*)out_attn;
    float4 v = p4[i];
    v.x *= inv; v.y *= inv; v.z *= inv; v.w *= inv;
    p4[i] = v;
}

// ---------------- launch ----------------
extern "C" void kernel_launch(void* const* d_in, const int* in_sizes, int n_in,
                              void* d_out, int out_size) {
    const float* x = (const float*)d_in[0];
    const float* noise = (const float*)d_in[1];
    const float* mu = (const float*)d_in[2];
    const float* sigma = (const float*)d_in[3];
    const float* Wq = (const float*)d_in[4];
    const float* Wk = (const float*)d_in[5];
    const float* Wv = (const float*)d_in[6];
    const float* Wih = (const float*)d_in[7];
    const float* Whh = (const float*)d_in[8];
    const float* bih = (const float*)d_in[9];
    const float* bhh = (const float*)d_in[10];
    const float* ling = (const float*)d_in[11];
    const float* linb = (const float*)d_in[12];
    const float* lsg = (const float*)d_in[13];
    const float* lsb = (const float*)d_in[14];
    const float* ffg = (const float*)d_in[15];
    const float* ffb = (const float*)d_in[16];
    const float* W1 = (const float*)d_in[17];
    const float* fb1 = (const float*)d_in[18];
    const float* W2 = (const float*)d_in[19];
    const float* fb2 = (const float*)d_in[20];

    float* out = (float*)d_out;
    float* out_slots = out;                     // [B,K,D]
    float* out_attn = out + Bc * Kc * Dc;       // [B,K,P]

    cudaFuncSetAttribute(k_proj, cudaFuncAttributeMaxDynamicSharedMemorySize, PROJ_SMEM);

    k_init<<<256, 256>>>(noise, mu, sigma, Wq, Wih, Whh, W1, W2);
    k_proj<<<(Bc * Pc) / 256, 256, PROJ_SMEM>>>(x, Wk, Wv, ling, linb);
    for (int it = 0; it < ITERS_C; it++) {
        int last = (it == ITERS_C - 1) ? 1 : 0;
        k_q<<<Bc * Kc, 64>>>(lsg, lsb);
        k_attn<<<(Bc * Pc) / 256, 256>>>(out_attn, last);
        k_gru<<<Bc * Kc, 64>>>(bih, bhh, ffg, ffb, fb1, fb2, out_slots, last);
    }
    k_scale<<<(Bc * Kc * Pc) / 1024, 256>>>(out_attn);
}